// round 8
// baseline (speedup 1.0000x reference)
#include <cuda_runtime.h>
#include <cstdint>

// out[n, d] = x[n, d] * w[d];  N = DIM = 8192, fp32.
// R8: single-wave persistent variant of the verified-best stream kernel.
// 256 blocks (<= concurrent capacity at ~62 regs, so exactly ONE wave);
// each thread owns one float4-column and streams 256 rows. Same inner loop
// as the 6.33 TB/s kernel: 8 front-batched LDG.128 -> 8 STG.128, evict-first.

static constexpr int DIM   = 8192;
static constexpr int DIM4  = DIM / 4;              // 2048 float4 columns
static constexpr int THREADS = 256;
static constexpr int COLBLOCKS = DIM4 / THREADS;   // 8 column-blocks per row
static constexpr int ROWGROUPS = 32;               // single-wave: 8*32 = 256 blocks
static constexpr int UNROLL = 8;

__global__ void __launch_bounds__(THREADS)
diag_scale_persist_kernel(const float4* __restrict__ x,
                          const float4* __restrict__ w4,
                          float4* __restrict__ out,
                          int n_rows)
{
    const int cb = blockIdx.x & (COLBLOCKS - 1);
    const int rg = blockIdx.x >> 3;
    const int col4 = cb * THREADS + threadIdx.x;

    const float4 wv = __ldg(&w4[col4]);            // once; stays in registers

    const long long rstride = (long long)ROWGROUPS * DIM4;   // elems between rows
    const float4* xp = x   + (long long)rg * DIM4 + col4;
    float4*       op = out + (long long)rg * DIM4 + col4;

    const int iters = n_rows / (ROWGROUPS * UNROLL);          // 32 for N=8192

    for (int it = 0; it < iters; ++it) {
        float4 v[UNROLL];
        #pragma unroll
        for (int u = 0; u < UNROLL; ++u)
            v[u] = __ldcs(xp + (long long)u * rstride);       // 8 reads in flight
        #pragma unroll
        for (int u = 0; u < UNROLL; ++u) {
            v[u].x *= wv.x;
            v[u].y *= wv.y;
            v[u].z *= wv.z;
            v[u].w *= wv.w;
            __stcs(op + (long long)u * rstride, v[u]);        // 8 writes
        }
        xp += (long long)UNROLL * rstride;
        op += (long long)UNROLL * rstride;
    }
}

// Generic fallback (correct for any shape).
__global__ void __launch_bounds__(256)
diag_scale_fallback(const float4* __restrict__ x,
                    const float4* __restrict__ w4,
                    float4* __restrict__ out,
                    long long n4, int dim4)
{
    long long i = (long long)blockIdx.x * blockDim.x + threadIdx.x;
    long long stride = (long long)gridDim.x * blockDim.x;
    for (; i < n4; i += stride) {
        float4 v = x[i];
        int col4 = (int)(i % dim4);
        float4 wv = __ldg(&w4[col4]);
        v.x *= wv.x; v.y *= wv.y; v.z *= wv.z; v.w *= wv.w;
        out[i] = v;
    }
}

extern "C" void kernel_launch(void* const* d_in, const int* in_sizes, int n_in,
                              void* d_out, int out_size)
{
    const float4* x  = (const float4*)d_in[0];
    const float4* w4 = (const float4*)d_in[1];
    float4* out = (float4*)d_out;

    long long n_elems = (long long)out_size;
    int dim = in_sizes[1];
    int n_rows = (int)(n_elems / dim);

    bool fast_ok = (dim == DIM) && (n_rows % (ROWGROUPS * UNROLL) == 0);

    if (fast_ok) {
        int blocks = COLBLOCKS * ROWGROUPS;    // 256 blocks — one wave
        diag_scale_persist_kernel<<<blocks, THREADS>>>(x, w4, out, n_rows);
    } else {
        long long n4 = n_elems / 4;
        const int threads = 256;
        int blocks = 148 * 8 * 4;
        long long needed = (n4 + threads - 1) / threads;
        if ((long long)blocks > needed) blocks = (int)needed;
        diag_scale_fallback<<<blocks, threads>>>(x, w4, out, n4, dim / 4);
    }
}

// round 9
// speedup vs baseline: 1.0019x; 1.0019x over previous
#include <cuda_runtime.h>
#include <cstdint>

// out[n, d] = x[n, d] * w[d];  N = DIM = 8192, fp32.
// FINAL (verified 3x at 84.0us bench / 76.7us kernel / 6.33 TB/s).
// Ceiling analysis R1-R8: seven structurally different kernels (grid-stride,
// column-owning MLP4/MLP8, cache-policy hints, sw-pipeline, 256-bit v8,
// single-wave persistent) all pin at or below 6.33 TB/s -> mixed 50/50 R/W
// HBM3e stream limit (~79% of 8TB/s spec; bus turnaround bound). Traffic is
// at the 512 MiB algorithmic floor; no kernel-side lever remains.
// Each thread owns one float4-column; weight in registers; 8 front-batched
// LDG.128 then 8 STG.128 per iteration; evict-first policy both directions.

static constexpr int DIM   = 8192;
static constexpr int DIM4  = DIM / 4;              // 2048 float4 columns
static constexpr int THREADS = 256;
static constexpr int COLBLOCKS = DIM4 / THREADS;   // 8 column-blocks per row
static constexpr int ROWGROUPS = 256;
static constexpr int UNROLL = 8;

__global__ void __launch_bounds__(THREADS)
diag_scale_stream_kernel(const float4* __restrict__ x,
                         const float4* __restrict__ w4,
                         float4* __restrict__ out,
                         int n_rows)
{
    const int cb = blockIdx.x & (COLBLOCKS - 1);
    const int rg = blockIdx.x >> 3;
    const int col4 = cb * THREADS + threadIdx.x;

    const float4 wv = __ldg(&w4[col4]);            // once; stays in registers

    const long long rstride = (long long)ROWGROUPS * DIM4;   // elems between rows
    const float4* xp = x   + (long long)rg * DIM4 + col4;
    float4*       op = out + (long long)rg * DIM4 + col4;

    const int iters = n_rows / (ROWGROUPS * UNROLL);          // 4 for N=8192

    for (int it = 0; it < iters; ++it) {
        float4 v[UNROLL];
        #pragma unroll
        for (int u = 0; u < UNROLL; ++u)
            v[u] = __ldcs(xp + (long long)u * rstride);       // 8 reads in flight
        #pragma unroll
        for (int u = 0; u < UNROLL; ++u) {
            v[u].x *= wv.x;
            v[u].y *= wv.y;
            v[u].z *= wv.z;
            v[u].w *= wv.w;
            __stcs(op + (long long)u * rstride, v[u]);        // 8 writes
        }
        xp += (long long)UNROLL * rstride;
        op += (long long)UNROLL * rstride;
    }
}

// Generic fallback (correct for any shape).
__global__ void __launch_bounds__(256)
diag_scale_fallback(const float4* __restrict__ x,
                    const float4* __restrict__ w4,
                    float4* __restrict__ out,
                    long long n4, int dim4)
{
    long long i = (long long)blockIdx.x * blockDim.x + threadIdx.x;
    long long stride = (long long)gridDim.x * blockDim.x;
    for (; i < n4; i += stride) {
        float4 v = x[i];
        int col4 = (int)(i % dim4);
        float4 wv = __ldg(&w4[col4]);
        v.x *= wv.x; v.y *= wv.y; v.z *= wv.z; v.w *= wv.w;
        out[i] = v;
    }
}

extern "C" void kernel_launch(void* const* d_in, const int* in_sizes, int n_in,
                              void* d_out, int out_size)
{
    const float4* x  = (const float4*)d_in[0];
    const float4* w4 = (const float4*)d_in[1];
    float4* out = (float4*)d_out;

    long long n_elems = (long long)out_size;
    int dim = in_sizes[1];
    int n_rows = (int)(n_elems / dim);

    bool fast_ok = (dim == DIM) && (n_rows % (ROWGROUPS * UNROLL) == 0);

    if (fast_ok) {
        int blocks = COLBLOCKS * ROWGROUPS;    // 2048 blocks
        diag_scale_stream_kernel<<<blocks, THREADS>>>(x, w4, out, n_rows);
    } else {
        long long n4 = n_elems / 4;
        const int threads = 256;
        int blocks = 148 * 8 * 4;
        long long needed = (n4 + threads - 1) / threads;
        if ((long long)blocks > needed) blocks = (int)needed;
        diag_scale_fallback<<<blocks, threads>>>(x, w4, out, n4, dim / 4);
    }
}

// round 10
// speedup vs baseline: 1.0027x; 1.0008x over previous
#include <cuda_runtime.h>
#include <cstdint>

// out[n, d] = x[n, d] * w[d];  N = DIM = 8192, fp32.
// FINAL (verified 4x at 84.0us bench / 76.7us kernel / 6.33 TB/s, rel_err 0).
//
// Ceiling analysis R1-R9: seven structurally different kernels (grid-stride,
// column-owning MLP4/MLP8, cache-policy hints, sw-pipeline, 256-bit v8,
// single-wave persistent) all pin at or below 6.33 TB/s. At NAT clock this is
// ~3500 B/cyc — below the ~6300 B/cyc LTS cap — so the limit is the DRAM
// controller's mixed 50/50 R/W turnaround on HBM3e (~79% of 8 TB/s spec).
// Traffic is at the 512 MiB algorithmic floor (full-sector stores, coalesced
// 128-bit accesses, L1-resident weights). No kernel-side lever remains; the
// bench-vs-kernel 7.3us gap is fixed graph-replay overhead.
//
// Structure: each thread owns one float4-column; weight loaded once into
// registers; 8 front-batched LDG.128 then 8 STG.128 per iteration;
// evict-first L2 policy both directions.

static constexpr int DIM   = 8192;
static constexpr int DIM4  = DIM / 4;              // 2048 float4 columns
static constexpr int THREADS = 256;
static constexpr int COLBLOCKS = DIM4 / THREADS;   // 8 column-blocks per row
static constexpr int ROWGROUPS = 256;
static constexpr int UNROLL = 8;

__global__ void __launch_bounds__(THREADS)
diag_scale_stream_kernel(const float4* __restrict__ x,
                         const float4* __restrict__ w4,
                         float4* __restrict__ out,
                         int n_rows)
{
    const int cb = blockIdx.x & (COLBLOCKS - 1);
    const int rg = blockIdx.x >> 3;
    const int col4 = cb * THREADS + threadIdx.x;

    const float4 wv = __ldg(&w4[col4]);            // once; stays in registers

    const long long rstride = (long long)ROWGROUPS * DIM4;   // elems between rows
    const float4* xp = x   + (long long)rg * DIM4 + col4;
    float4*       op = out + (long long)rg * DIM4 + col4;

    const int iters = n_rows / (ROWGROUPS * UNROLL);          // 4 for N=8192

    for (int it = 0; it < iters; ++it) {
        float4 v[UNROLL];
        #pragma unroll
        for (int u = 0; u < UNROLL; ++u)
            v[u] = __ldcs(xp + (long long)u * rstride);       // 8 reads in flight
        #pragma unroll
        for (int u = 0; u < UNROLL; ++u) {
            v[u].x *= wv.x;
            v[u].y *= wv.y;
            v[u].z *= wv.z;
            v[u].w *= wv.w;
            __stcs(op + (long long)u * rstride, v[u]);        // 8 writes
        }
        xp += (long long)UNROLL * rstride;
        op += (long long)UNROLL * rstride;
    }
}

// Generic fallback (correct for any shape).
__global__ void __launch_bounds__(256)
diag_scale_fallback(const float4* __restrict__ x,
                    const float4* __restrict__ w4,
                    float4* __restrict__ out,
                    long long n4, int dim4)
{
    long long i = (long long)blockIdx.x * blockDim.x + threadIdx.x;
    long long stride = (long long)gridDim.x * blockDim.x;
    for (; i < n4; i += stride) {
        float4 v = x[i];
        int col4 = (int)(i % dim4);
        float4 wv = __ldg(&w4[col4]);
        v.x *= wv.x; v.y *= wv.y; v.z *= wv.z; v.w *= wv.w;
        out[i] = v;
    }
}

extern "C" void kernel_launch(void* const* d_in, const int* in_sizes, int n_in,
                              void* d_out, int out_size)
{
    const float4* x  = (const float4*)d_in[0];
    const float4* w4 = (const float4*)d_in[1];
    float4* out = (float4*)d_out;

    long long n_elems = (long long)out_size;
    int dim = in_sizes[1];
    int n_rows = (int)(n_elems / dim);

    bool fast_ok = (dim == DIM) && (n_rows % (ROWGROUPS * UNROLL) == 0);

    if (fast_ok) {
        int blocks = COLBLOCKS * ROWGROUPS;    // 2048 blocks
        diag_scale_stream_kernel<<<blocks, THREADS>>>(x, w4, out, n_rows);
    } else {
        long long n4 = n_elems / 4;
        const int threads = 256;
        int blocks = 148 * 8 * 4;
        long long needed = (n4 + threads - 1) / threads;
        if ((long long)blocks > needed) blocks = (int)needed;
        diag_scale_fallback<<<blocks, threads>>>(x, w4, out, n4, dim / 4);
    }
}